// round 3
// baseline (speedup 1.0000x reference)
#include <cuda_runtime.h>
#include <cuda_bf16.h>
#include <stdint.h>

// SkipGram negative-sampling loss:
//   pos = logsigmoid(dot(Wh[t], Wo[c]))
//   neg = logsigmoid(-sum_k dot(Wh[t], Wo[neg_k]))   (sum over K BEFORE logsigmoid)
//   out = -(sum pos + sum neg) / N
//
// One warp per pair; each lane owns a float4 slice of the D=128 row.
// Warp-uniform indices loaded once by lanes 0..6 and shuffled.
// Deterministic two-stage reduction (no float atomics).

#define D 128
#define K 5
#define NTHREADS 256
#define WARPS_PER_BLOCK (NTHREADS / 32)
#define NBLOCKS 1184          // 8 blocks/SM on 148 SMs
#define TOTAL_WARPS (NBLOCKS * WARPS_PER_BLOCK)

__device__ float g_partials[NBLOCKS];

__device__ __forceinline__ float logsig(float x) {
    // log(sigmoid(x)) = min(x, 0) - log1p(exp(-|x|)); stable for all x
    return fminf(x, 0.0f) - log1pf(expf(-fabsf(x)));
}

__device__ __forceinline__ float dot4(float4 a, float4 b) {
    return a.x * b.x + a.y * b.y + a.z * b.z + a.w * b.w;
}

__global__ __launch_bounds__(NTHREADS)
void skipgram_loss_kernel(const int* __restrict__ targets,
                          const int* __restrict__ contexts,
                          const int* __restrict__ negs,
                          const float* __restrict__ Wh,
                          const float* __restrict__ Wo,
                          int n) {
    const int lane = threadIdx.x & 31;
    const int warp_global = (blockIdx.x * NTHREADS + threadIdx.x) >> 5;

    float acc = 0.0f;

    for (int i = warp_global; i < n; i += TOTAL_WARPS) {
        // Lanes 0..6 fetch the 7 warp-uniform indices; broadcast via shuffle.
        // lane 0: targets[i], lane 1: contexts[i], lanes 2..6: negs[i*K .. i*K+4]
        int idx = 0;
        if (lane == 0)      idx = __ldg(targets + i);
        else if (lane == 1) idx = __ldg(contexts + i);
        else if (lane < 7)  idx = __ldg(negs + (int64_t)i * K + (lane - 2));

        const int t = __shfl_sync(0xFFFFFFFFu, idx, 0);
        const int c = __shfl_sync(0xFFFFFFFFu, idx, 1);
        int nk[K];
#pragma unroll
        for (int k = 0; k < K; k++)
            nk[k] = __shfl_sync(0xFFFFFFFFu, idx, 2 + k);

        // Target row slice (reused 6x)
        const float4 tv = __ldg((const float4*)(Wh + (size_t)t * D) + lane);
        // Positive context
        const float4 cv = __ldg((const float4*)(Wo + (size_t)c * D) + lane);

        // Negatives: issue all loads before consuming (MLP to cover L2 latency)
        float4 nv[K];
#pragma unroll
        for (int k = 0; k < K; k++)
            nv[k] = __ldg((const float4*)(Wo + (size_t)nk[k] * D) + lane);

        float pos = dot4(tv, cv);
        float neg = 0.0f;
#pragma unroll
        for (int k = 0; k < K; k++) neg += dot4(tv, nv[k]);

        // Warp tree-reduce both sums (deterministic, fixed order)
#pragma unroll
        for (int off = 16; off > 0; off >>= 1) {
            pos += __shfl_down_sync(0xFFFFFFFFu, pos, off);
            neg += __shfl_down_sync(0xFFFFFFFFu, neg, off);
        }

        if (lane == 0)
            acc += logsig(pos) + logsig(-neg);
    }

    // Block reduction: lane 0 of each warp contributes (fixed order -> deterministic)
    __shared__ float s[WARPS_PER_BLOCK];
    if (lane == 0) s[threadIdx.x >> 5] = acc;
    __syncthreads();
    if (threadIdx.x == 0) {
        float b = 0.0f;
#pragma unroll
        for (int w = 0; w < WARPS_PER_BLOCK; w++) b += s[w];
        g_partials[blockIdx.x] = b;
    }
}

__global__ __launch_bounds__(256)
void finalize_kernel(float* __restrict__ out, int n) {
    __shared__ float s[256];
    float v = 0.0f;
    for (int i = threadIdx.x; i < NBLOCKS; i += 256)
        v += g_partials[i];
    s[threadIdx.x] = v;
    __syncthreads();
#pragma unroll
    for (int off = 128; off > 0; off >>= 1) {
        if (threadIdx.x < off) s[threadIdx.x] += s[threadIdx.x + off];
        __syncthreads();
    }
    if (threadIdx.x == 0)
        out[0] = -s[0] / (float)n;
}

extern "C" void kernel_launch(void* const* d_in, const int* in_sizes, int n_in,
                              void* d_out, int out_size) {
    const int*   targets  = (const int*)d_in[0];   // targets_1_pos [N] int32
    const int*   contexts = (const int*)d_in[1];   // contexts_1_pos [N] int32
    const int*   negs     = (const int*)d_in[2];   // contexts_0_pos_samples [N,K] int32
    const float* Wh       = (const float*)d_in[3]; // W_hidden [V,D]
    const float* Wo       = (const float*)d_in[4]; // W_output [V,D]
    float* out = (float*)d_out;

    const int n = in_sizes[0];

    skipgram_loss_kernel<<<NBLOCKS, NTHREADS>>>(targets, contexts, negs, Wh, Wo, n);
    finalize_kernel<<<1, 256>>>(out, n);
}